// round 14
// baseline (speedup 1.0000x reference)
#include <cuda_runtime.h>
#include <cstdint>

#define Nn 32
#define Cc 64
#define Hh 112
#define Wd 112
#define HW (Hh*Wd)            // 12544
#define NHW (Nn*HW)           // 401408
#define TOT (Nn*Cc*HW)        // 25690112
#define BN_EPS 1e-5

typedef unsigned long long u64;

// ---------------- scratch (device globals) -------------------------------------
__device__ u64       g_wbits[Cc*9];     // packed weight signs
__device__ float     g_wasum[Cc*9*2];   // per-(co,tap,half) partial |w| sums
__device__ long long g_sum[Cc];
__device__ long long g_ss[Cc];
__device__ short     g_conv[TOT];       // NHWC [n][p][c] int16 conv result

// ---------------- K0: pack W via ballot (144 blocks, 1 warp per (co,tap,half)) -
__global__ __launch_bounds__(256) void packW_k(const float* __restrict__ W) {
    int gw   = blockIdx.x*8 + (threadIdx.x >> 5);   // 0..1151
    int lane = threadIdx.x & 31;
    int co   = gw / 18;
    int rem  = gw - co*18;
    int tap  = rem >> 1;
    int half = rem & 1;
    float w = W[(size_t)(co*Cc + half*32 + lane)*9 + tap];
    unsigned bits = __ballot_sync(0xffffffffu, (__float_as_uint(w) >> 31) & 1u);
    float a = fabsf(w);
    #pragma unroll
    for (int o = 16; o; o >>= 1) a += __shfl_xor_sync(0xffffffffu, a, o);
    if (lane == 0) {
        ((unsigned*)g_wbits)[(co*9 + tap)*2 + half] = bits;  // LE: half0 = ch 0-31
        g_wasum[(co*9 + tap)*2 + half] = a;
    }
    if (blockIdx.x == 0 && threadIdx.x < Cc) {
        g_sum[threadIdx.x] = 0; g_ss[threadIdx.x] = 0;
    }
}

#define WD0(t) (64 - 2*__popcll(wb0[t]))
#define WD1(t) (64 - 2*__popcll(wb1[t]))

// ---------------- K1: fused pack + popcount conv + BN stats --------------------
// 16x16 tile per block, channel-pair per thread, single-pixel u64 sliding window,
// lazy border math (no wd arrays) -> ~80 regs -> 3 blocks/SM without spills, so
// one block's halo-pack LDG latency hides under other blocks' popcount ALU.
__global__ __launch_bounds__(256, 3) void conv_k(const float* __restrict__ x) {
    __shared__ u64 xs[18*18];
    __shared__ int st[4][8][32];

    int tid  = threadIdx.x;
    int pair = tid & 31;
    int grp  = tid >> 5;
    int n  = blockIdx.z;
    int h0 = blockIdx.y * 16, w0 = blockIdx.x * 16;

    // fused halo pack: read 64 channel floats per halo pixel, pack sign bits
    const float* xn = x + (size_t)n*Cc*HW;
    for (int j = tid; j < 18*18; j += 256) {
        int lh = j / 18, lw = j - lh*18;
        int gh = h0 + lh - 1, gw = w0 + lw - 1;
        u64 v = 0ull;
        if (gh >= 0 && gh < Hh && gw >= 0 && gw < Wd) {
            const float* px = xn + gh*Wd + gw;
            unsigned lo = 0, hi = 0;
            #pragma unroll
            for (int c = 0; c < 32; c++)
                lo |= (__float_as_uint(__ldg(px + (size_t)c*HW)) >> 31) << c;
            #pragma unroll
            for (int c = 0; c < 32; c++)
                hi |= (__float_as_uint(__ldg(px + (size_t)(c+32)*HW)) >> 31) << c;
            v = ((u64)hi << 32) | lo;
        }
        xs[j] = v;
    }

    int c0 = pair*2;
    u64 wb0[9], wb1[9];
    #pragma unroll
    for (int t = 0; t < 9; t++) {
        wb0[t] = g_wbits[c0*9 + t];
        wb1[t] = g_wbits[(c0+1)*9 + t];
    }
    __syncthreads();

    const bool wleft  = (w0 == 0);
    const bool wright = (w0 == Wd-16);
    int as0 = 0, ass0 = 0, as1 = 0, ass1 = 0;

    #pragma unroll
    for (int r = 0; r < 2; r++) {
        int ohl = grp*2 + r;
        int oh  = h0 + ohl;
        int rp  = (oh == 0) ? 1 : ((oh == Hh-1) ? 2 : 0);

        // lazy border constants (uniform per warp; interior rows skip)
        int base0 = 576, base1 = 576;
        if (rp == 1) {
            base0 -= WD0(0) + WD0(1) + WD0(2);
            base1 -= WD1(0) + WD1(1) + WD1(2);
        } else if (rp == 2) {
            base0 -= WD0(6) + WD0(7) + WD0(8);
            base1 -= WD1(6) + WD1(7) + WD1(8);
        }
        int cw0 = 0, cw1 = 0, ce0 = 0, ce1 = 0;
        if (wleft) {
            cw0 = WD0(3); cw1 = WD1(3);
            if (rp != 1) { cw0 += WD0(0); cw1 += WD1(0); }
            if (rp != 2) { cw0 += WD0(6); cw1 += WD1(6); }
        }
        if (wright) {
            ce0 = WD0(5); ce1 = WD1(5);
            if (rp != 1) { ce0 += WD0(2); ce1 += WD1(2); }
            if (rp != 2) { ce0 += WD0(8); ce1 += WD1(8); }
        }

        const u64* r0p = &xs[ohl*18];
        const u64* r1p = r0p + 18;
        const u64* r2p = r1p + 18;
        u64 x00 = r0p[0], x01 = r0p[1];
        u64 x10 = r1p[0], x11 = r1p[1];
        u64 x20 = r2p[0], x21 = r2p[1];

        unsigned* op = ((unsigned*)g_conv) + ((size_t)n*HW + (size_t)oh*Wd + w0)*32 + pair;

        #pragma unroll
        for (int w = 0; w < 16; w++) {
            u64 x02 = r0p[w+2], x12 = r1p[w+2], x22 = r2p[w+2];
            int pc0 = __popcll(x00^wb0[0]) + __popcll(x01^wb0[1]) + __popcll(x02^wb0[2])
                    + __popcll(x10^wb0[3]) + __popcll(x11^wb0[4]) + __popcll(x12^wb0[5])
                    + __popcll(x20^wb0[6]) + __popcll(x21^wb0[7]) + __popcll(x22^wb0[8]);
            int pc1 = __popcll(x00^wb1[0]) + __popcll(x01^wb1[1]) + __popcll(x02^wb1[2])
                    + __popcll(x10^wb1[3]) + __popcll(x11^wb1[4]) + __popcll(x12^wb1[5])
                    + __popcll(x20^wb1[6]) + __popcll(x21^wb1[7]) + __popcll(x22^wb1[8]);
            int s0 = base0 - 2*pc0;
            int s1 = base1 - 2*pc1;
            if (w == 0  && wleft)  { s0 -= cw0; s1 -= cw1; }
            if (w == 15 && wright) { s0 -= ce0; s1 -= ce1; }

            as0 += s0; ass0 += s0*s0;
            as1 += s1; ass1 += s1*s1;
            *op = ((unsigned)s0 & 0xFFFFu) | ((unsigned)s1 << 16);
            op += 32;

            x00 = x01; x01 = x02;
            x10 = x11; x11 = x12;
            x20 = x21; x21 = x22;
        }
    }

    st[0][grp][pair] = as0; st[1][grp][pair] = ass0;
    st[2][grp][pair] = as1; st[3][grp][pair] = ass1;
    __syncthreads();
    if (grp == 0) {
        int bs0=0, bss0=0, bs1=0, bss1=0;
        #pragma unroll
        for (int g = 0; g < 8; g++) {
            bs0 += st[0][g][pair]; bss0 += st[1][g][pair];
            bs1 += st[2][g][pair]; bss1 += st[3][g][pair];
        }
        atomicAdd((unsigned long long*)&g_sum[c0],   (unsigned long long)(long long)bs0);
        atomicAdd((unsigned long long*)&g_ss[c0],    (unsigned long long)(long long)bss0);
        atomicAdd((unsigned long long*)&g_sum[c0+1], (unsigned long long)(long long)bs1);
        atomicAdd((unsigned long long*)&g_ss[c0+1],  (unsigned long long)(long long)bss1);
    }
}

// ---------------- K2: affine fold (incl. alpha) + hardtanh + residual ----------
__global__ __launch_bounds__(256) void apply_k(const float* __restrict__ x,
                                               const float* __restrict__ gamma,
                                               const float* __restrict__ beta,
                                               float* __restrict__ out) {
    __shared__ float sA[Cc], sB[Cc];
    int tid = threadIdx.x;
    if (tid < Cc) {
        int c = tid;
        float t = 0.f;
        #pragma unroll
        for (int j = 0; j < 18; j++) t += g_wasum[c*18 + j];
        double a    = (double)(t / 576.f);
        double mean = (double)g_sum[c] / (double)NHW;
        double ex2  = (double)g_ss[c]  / (double)NHW;
        double var  = a*a*(ex2 - mean*mean);
        double rs   = 1.0 / sqrt(var + BN_EPS);
        double g    = (double)gamma[c];
        sA[c] = (float)(a * rs * g);
        sB[c] = (float)((double)beta[c] - a * mean * rs * g);
    }
    __syncthreads();

    size_t P = (size_t)blockIdx.x*256 + tid;      // global pixel id
    int n = (int)(P / HW);
    int p = (int)(P - (size_t)n*HW);
    const uint4* cb = (const uint4*)g_conv + P*8;           // 128B of NHWC shorts
    const float* xb = x   + (size_t)n*Cc*HW + p;
    float*       ob = out + (size_t)n*Cc*HW + p;

    #pragma unroll
    for (int q = 0; q < 8; q++) {
        uint4 v = cb[q];
        #pragma unroll
        for (int w = 0; w < 4; w++) {
            uint32_t u = (&v.x)[w];
            int cA = (q*4 + w)*2;
            int sv0 = (int)((int32_t)(u << 16) >> 16);
            int sv1 = (int)((int32_t)u >> 16);
            float r0 = fminf(fmaxf(fmaf((float)sv0, sA[cA],   sB[cA]),   -1.f), 1.f);
            float r1 = fminf(fmaxf(fmaf((float)sv1, sA[cA+1], sB[cA+1]), -1.f), 1.f);
            ob[(size_t)cA*HW]     = r0 + xb[(size_t)cA*HW];
            ob[(size_t)(cA+1)*HW] = r1 + xb[(size_t)(cA+1)*HW];
        }
    }
}

// ---------------- launcher ------------------------------------------------------
extern "C" void kernel_launch(void* const* d_in, const int* in_sizes, int n_in,
                              void* d_out, int out_size) {
    const float* x     = (const float*)d_in[0];
    const float* W     = (const float*)d_in[1];
    const float* gamma = (const float*)d_in[2];
    const float* beta  = (const float*)d_in[3];
    float* out = (float*)d_out;

    packW_k<<<144, 256>>>(W);
    conv_k<<<dim3(7, 7, Nn), 256>>>(x);
    apply_k<<<NHW/256, 256>>>(x, gamma, beta, out);
}

// round 15
// speedup vs baseline: 1.4113x; 1.4113x over previous
#include <cuda_runtime.h>
#include <cstdint>

#define Nn 32
#define Cc 64
#define Hh 112
#define Wd 112
#define HW (Hh*Wd)            // 12544
#define NHW (Nn*HW)           // 401408
#define TOT (Nn*Cc*HW)        // 25690112
#define BN_EPS 1e-5

typedef unsigned long long u64;

// ---------------- scratch (device globals) -------------------------------------
__device__ u64       g_wbits[Cc*9];     // packed weight signs
__device__ float     g_wasum[Cc*9*2];   // per-(co,tap,half) partial |w| sums
__device__ long long g_sum[Cc];
__device__ long long g_ss[Cc];
__device__ short     g_conv[TOT];       // NHWC [n][p][c] int16 conv result

// ---------------- K0: pack W via ballot (144 blocks, 1 warp per (co,tap,half)) -
__global__ __launch_bounds__(256) void packW_k(const float* __restrict__ W) {
    int gw   = blockIdx.x*8 + (threadIdx.x >> 5);   // 0..1151
    int lane = threadIdx.x & 31;
    int co   = gw / 18;
    int rem  = gw - co*18;
    int tap  = rem >> 1;
    int half = rem & 1;
    float w = W[(size_t)(co*Cc + half*32 + lane)*9 + tap];
    unsigned bits = __ballot_sync(0xffffffffu, (__float_as_uint(w) >> 31) & 1u);
    float a = fabsf(w);
    #pragma unroll
    for (int o = 16; o; o >>= 1) a += __shfl_xor_sync(0xffffffffu, a, o);
    if (lane == 0) {
        ((unsigned*)g_wbits)[(co*9 + tap)*2 + half] = bits;  // LE: half0 = ch 0-31
        g_wasum[(co*9 + tap)*2 + half] = a;
    }
    if (blockIdx.x == 0 && threadIdx.x < Cc) {
        g_sum[threadIdx.x] = 0; g_ss[threadIdx.x] = 0;
    }
}

#define WD0(t) (64 - 2*__popcll(wb0[t]))
#define WD1(t) (64 - 2*__popcll(wb1[t]))

// 9-tap XNOR popcount for one channel
#define PC9(wb, c0_, c1_, c2_, c3_, c4_, c5_, c6_, c7_, c8_) \
    (__popcll((c0_)^(wb)[0]) + __popcll((c1_)^(wb)[1]) + __popcll((c2_)^(wb)[2]) \
   + __popcll((c3_)^(wb)[3]) + __popcll((c4_)^(wb)[4]) + __popcll((c5_)^(wb)[5]) \
   + __popcll((c6_)^(wb)[6]) + __popcll((c7_)^(wb)[7]) + __popcll((c8_)^(wb)[8]))

// ---------------- K1: fused pack + popcount conv + BN stats --------------------
// 16x16 tile per block, channel-pair per thread, LDS.128 2-pixel inner loop
// (round-13 winner). Halo pack restructured: depth-1 float4 row-segment tasks
// (72 vector tasks x 4px + 36 scalar edge tasks) for 4x bytes-in-flight.
__global__ __launch_bounds__(256, 2) void conv_k(const float* __restrict__ x) {
    __shared__ __align__(16) u64 xs[18*18];
    __shared__ int st[4][8][32];

    int tid  = threadIdx.x;
    int pair = tid & 31;
    int grp  = tid >> 5;
    int n  = blockIdx.z;
    int h0 = blockIdx.y * 16, w0 = blockIdx.x * 16;

    // ---- fused halo pack, depth-1 task decomposition ----
    const float* xn = x + (size_t)n*Cc*HW;
    if (tid < 72) {
        // vector task: 4 pixels at gw = w0 + seg*4 (16B-aligned), row 0..17
        int row = tid >> 2, seg = tid & 3;
        int gh = h0 + row - 1;
        u64 v0 = 0, v1 = 0, v2 = 0, v3 = 0;
        if (gh >= 0 && gh < Hh) {
            const float4* px = (const float4*)(xn + (size_t)gh*Wd + (w0 + seg*4));
            unsigned lo0=0, lo1=0, lo2=0, lo3=0;
            unsigned hi0=0, hi1=0, hi2=0, hi3=0;
            #pragma unroll
            for (int c = 0; c < 32; c++) {
                float4 f = __ldg(px + (size_t)c*(HW/4));
                lo0 |= (__float_as_uint(f.x) >> 31) << c;
                lo1 |= (__float_as_uint(f.y) >> 31) << c;
                lo2 |= (__float_as_uint(f.z) >> 31) << c;
                lo3 |= (__float_as_uint(f.w) >> 31) << c;
            }
            #pragma unroll
            for (int c = 0; c < 32; c++) {
                float4 f = __ldg(px + (size_t)(c+32)*(HW/4));
                hi0 |= (__float_as_uint(f.x) >> 31) << c;
                hi1 |= (__float_as_uint(f.y) >> 31) << c;
                hi2 |= (__float_as_uint(f.z) >> 31) << c;
                hi3 |= (__float_as_uint(f.w) >> 31) << c;
            }
            v0 = ((u64)hi0 << 32) | lo0;
            v1 = ((u64)hi1 << 32) | lo1;
            v2 = ((u64)hi2 << 32) | lo2;
            v3 = ((u64)hi3 << 32) | lo3;
        }
        u64* dst = &xs[row*18 + 1 + seg*4];
        dst[0] = v0; dst[1] = v1; dst[2] = v2; dst[3] = v3;
    } else if (tid < 108) {
        // scalar edge task: lw = 0 (gw = w0-1) or lw = 17 (gw = w0+16)
        int s2   = tid - 72;
        int row  = s2 >> 1, side = s2 & 1;
        int gh = h0 + row - 1;
        int gw = side ? (w0 + 16) : (w0 - 1);
        u64 v = 0ull;
        if (gh >= 0 && gh < Hh && gw >= 0 && gw < Wd) {
            const float* px = xn + (size_t)gh*Wd + gw;
            unsigned lo = 0, hi = 0;
            #pragma unroll
            for (int c = 0; c < 32; c++)
                lo |= (__float_as_uint(__ldg(px + (size_t)c*HW)) >> 31) << c;
            #pragma unroll
            for (int c = 0; c < 32; c++)
                hi |= (__float_as_uint(__ldg(px + (size_t)(c+32)*HW)) >> 31) << c;
            v = ((u64)hi << 32) | lo;
        }
        xs[row*18 + (side ? 17 : 0)] = v;
    }

    int c0 = pair*2;
    u64 wb0[9], wb1[9];
    #pragma unroll
    for (int t = 0; t < 9; t++) {
        wb0[t] = g_wbits[c0*9 + t];
        wb1[t] = g_wbits[(c0+1)*9 + t];
    }
    __syncthreads();

    const bool wleft  = (w0 == 0);
    const bool wright = (w0 == Wd-16);
    int as0 = 0, ass0 = 0, as1 = 0, ass1 = 0;

    #pragma unroll
    for (int r = 0; r < 2; r++) {
        int ohl = grp*2 + r;
        int oh  = h0 + ohl;
        int rp  = (oh == 0) ? 1 : ((oh == Hh-1) ? 2 : 0);

        // lazy border constants (uniform per warp; interior rows skip)
        int base0 = 576, base1 = 576;
        if (rp == 1) {
            base0 -= WD0(0) + WD0(1) + WD0(2);
            base1 -= WD1(0) + WD1(1) + WD1(2);
        } else if (rp == 2) {
            base0 -= WD0(6) + WD0(7) + WD0(8);
            base1 -= WD1(6) + WD1(7) + WD1(8);
        }
        int cw0 = 0, cw1 = 0, ce0 = 0, ce1 = 0;
        if (wleft) {
            cw0 = WD0(3); cw1 = WD1(3);
            if (rp != 1) { cw0 += WD0(0); cw1 += WD1(0); }
            if (rp != 2) { cw0 += WD0(6); cw1 += WD1(6); }
        }
        if (wright) {
            ce0 = WD0(5); ce1 = WD1(5);
            if (rp != 1) { ce0 += WD0(2); ce1 += WD1(2); }
            if (rp != 2) { ce0 += WD0(8); ce1 += WD1(8); }
        }

        const u64* r0p = &xs[ohl*18];
        const u64* r1p = r0p + 18;
        const u64* r2p = r1p + 18;
        ulonglong2 p0 = *(const ulonglong2*)&r0p[0];
        ulonglong2 p1 = *(const ulonglong2*)&r1p[0];
        ulonglong2 p2 = *(const ulonglong2*)&r2p[0];
        u64 x00 = p0.x, x01 = p0.y;
        u64 x10 = p1.x, x11 = p1.y;
        u64 x20 = p2.x, x21 = p2.y;

        unsigned* op = ((unsigned*)g_conv) + ((size_t)n*HW + (size_t)oh*Wd + w0)*32 + pair;

        #pragma unroll
        for (int w = 0; w < 16; w += 2) {
            ulonglong2 a0 = *(const ulonglong2*)&r0p[w+2];
            ulonglong2 a1 = *(const ulonglong2*)&r1p[w+2];
            ulonglong2 a2 = *(const ulonglong2*)&r2p[w+2];

            int sA0 = base0 - 2*PC9(wb0, x00,x01,a0.x, x10,x11,a1.x, x20,x21,a2.x);
            int sA1 = base1 - 2*PC9(wb1, x00,x01,a0.x, x10,x11,a1.x, x20,x21,a2.x);
            int sB0 = base0 - 2*PC9(wb0, x01,a0.x,a0.y, x11,a1.x,a1.y, x21,a2.x,a2.y);
            int sB1 = base1 - 2*PC9(wb1, x01,a0.x,a0.y, x11,a1.x,a1.y, x21,a2.x,a2.y);

            if (w == 0 && wleft)    { sA0 -= cw0; sA1 -= cw1; }
            if (w == 14 && wright)  { sB0 -= ce0; sB1 -= ce1; }

            as0 += sA0 + sB0; ass0 += sA0*sA0 + sB0*sB0;
            as1 += sA1 + sB1; ass1 += sA1*sA1 + sB1*sB1;

            op[0]  = ((unsigned)sA0 & 0xFFFFu) | ((unsigned)sA1 << 16);
            op[32] = ((unsigned)sB0 & 0xFFFFu) | ((unsigned)sB1 << 16);
            op += 64;

            x00 = a0.x; x01 = a0.y;
            x10 = a1.x; x11 = a1.y;
            x20 = a2.x; x21 = a2.y;
        }
    }

    st[0][grp][pair] = as0; st[1][grp][pair] = ass0;
    st[2][grp][pair] = as1; st[3][grp][pair] = ass1;
    __syncthreads();
    if (grp == 0) {
        int bs0=0, bss0=0, bs1=0, bss1=0;
        #pragma unroll
        for (int g = 0; g < 8; g++) {
            bs0 += st[0][g][pair]; bss0 += st[1][g][pair];
            bs1 += st[2][g][pair]; bss1 += st[3][g][pair];
        }
        atomicAdd((unsigned long long*)&g_sum[c0],   (unsigned long long)(long long)bs0);
        atomicAdd((unsigned long long*)&g_ss[c0],    (unsigned long long)(long long)bss0);
        atomicAdd((unsigned long long*)&g_sum[c0+1], (unsigned long long)(long long)bs1);
        atomicAdd((unsigned long long*)&g_ss[c0+1],  (unsigned long long)(long long)bss1);
    }
}

// ---------------- K2: affine fold (incl. alpha) + hardtanh + residual ----------
__global__ __launch_bounds__(256) void apply_k(const float* __restrict__ x,
                                               const float* __restrict__ gamma,
                                               const float* __restrict__ beta,
                                               float* __restrict__ out) {
    __shared__ float sA[Cc], sB[Cc];
    int tid = threadIdx.x;
    if (tid < Cc) {
        int c = tid;
        float t = 0.f;
        #pragma unroll
        for (int j = 0; j < 18; j++) t += g_wasum[c*18 + j];
        double a    = (double)(t / 576.f);
        double mean = (double)g_sum[c] / (double)NHW;
        double ex2  = (double)g_ss[c]  / (double)NHW;
        double var  = a*a*(ex2 - mean*mean);
        double rs   = 1.0 / sqrt(var + BN_EPS);
        double g    = (double)gamma[c];
        sA[c] = (float)(a * rs * g);
        sB[c] = (float)((double)beta[c] - a * mean * rs * g);
    }
    __syncthreads();

    size_t P = (size_t)blockIdx.x*256 + tid;      // global pixel id
    int n = (int)(P / HW);
    int p = (int)(P - (size_t)n*HW);
    const uint4* cb = (const uint4*)g_conv + P*8;           // 128B of NHWC shorts
    const float* xb = x   + (size_t)n*Cc*HW + p;
    float*       ob = out + (size_t)n*Cc*HW + p;

    #pragma unroll
    for (int q = 0; q < 8; q++) {
        uint4 v = cb[q];
        #pragma unroll
        for (int w = 0; w < 4; w++) {
            uint32_t u = (&v.x)[w];
            int cA = (q*4 + w)*2;
            int sv0 = (int)((int32_t)(u << 16) >> 16);
            int sv1 = (int)((int32_t)u >> 16);
            float r0 = fminf(fmaxf(fmaf((float)sv0, sA[cA],   sB[cA]),   -1.f), 1.f);
            float r1 = fminf(fmaxf(fmaf((float)sv1, sA[cA+1], sB[cA+1]), -1.f), 1.f);
            ob[(size_t)cA*HW]     = r0 + xb[(size_t)cA*HW];
            ob[(size_t)(cA+1)*HW] = r1 + xb[(size_t)(cA+1)*HW];
        }
    }
}

// ---------------- launcher ------------------------------------------------------
extern "C" void kernel_launch(void* const* d_in, const int* in_sizes, int n_in,
                              void* d_out, int out_size) {
    const float* x     = (const float*)d_in[0];
    const float* W     = (const float*)d_in[1];
    const float* gamma = (const float*)d_in[2];
    const float* beta  = (const float*)d_in[3];
    float* out = (float*)d_out;

    packW_k<<<144, 256>>>(W);
    conv_k<<<dim3(7, 7, Nn), 256>>>(x);
    apply_k<<<NHW/256, 256>>>(x, gamma, beta, out);
}

// round 16
// speedup vs baseline: 1.4921x; 1.0572x over previous
#include <cuda_runtime.h>
#include <cstdint>

#define Nn 32
#define Cc 64
#define Hh 112
#define Wd 112
#define HW (Hh*Wd)            // 12544
#define NHW (Nn*HW)           // 401408
#define TOT (Nn*Cc*HW)        // 25690112
#define BN_EPS 1e-5

typedef unsigned long long u64;

// ---------------- scratch (device globals) -------------------------------------
__device__ u64       g_wbits[Cc*9];     // packed weight signs
__device__ float     g_wasum[Cc*9*2];   // per-(co,tap,half) partial |w| sums
__device__ long long g_sum[Cc];
__device__ long long g_ss[Cc];
__device__ short     g_conv[TOT];       // NHWC [n][p][c] int16 conv result

// ---------------- K0: pack W via ballot (144 blocks, 1 warp per (co,tap,half)) -
__global__ __launch_bounds__(256) void packW_k(const float* __restrict__ W) {
    int gw   = blockIdx.x*8 + (threadIdx.x >> 5);   // 0..1151
    int lane = threadIdx.x & 31;
    int co   = gw / 18;
    int rem  = gw - co*18;
    int tap  = rem >> 1;
    int half = rem & 1;
    float w = W[(size_t)(co*Cc + half*32 + lane)*9 + tap];
    unsigned bits = __ballot_sync(0xffffffffu, (__float_as_uint(w) >> 31) & 1u);
    float a = fabsf(w);
    #pragma unroll
    for (int o = 16; o; o >>= 1) a += __shfl_xor_sync(0xffffffffu, a, o);
    if (lane == 0) {
        ((unsigned*)g_wbits)[(co*9 + tap)*2 + half] = bits;  // LE: half0 = ch 0-31
        g_wasum[(co*9 + tap)*2 + half] = a;
    }
    if (blockIdx.x == 0 && threadIdx.x < Cc) {
        g_sum[threadIdx.x] = 0; g_ss[threadIdx.x] = 0;
    }
}

#define WD0(t) (64 - 2*__popcll(wb0[t]))
#define WD1(t) (64 - 2*__popcll(wb1[t]))

// 9-tap XNOR popcount for one channel
#define PC9(wb, c0_, c1_, c2_, c3_, c4_, c5_, c6_, c7_, c8_) \
    (__popcll((c0_)^(wb)[0]) + __popcll((c1_)^(wb)[1]) + __popcll((c2_)^(wb)[2]) \
   + __popcll((c3_)^(wb)[3]) + __popcll((c4_)^(wb)[4]) + __popcll((c5_)^(wb)[5]) \
   + __popcll((c6_)^(wb)[6]) + __popcll((c7_)^(wb)[7]) + __popcll((c8_)^(wb)[8]))

// ---------------- K1: fused pack + popcount conv + BN stats --------------------
// 16x16 tile per block, channel-pair per thread, LDS.128 2-pixel inner loop
// (round-13 champion). Halo pack: sign-OR accumulation split into 4 independent
// partials per word (chain depth 8 instead of 32).
__global__ __launch_bounds__(256, 2) void conv_k(const float* __restrict__ x) {
    __shared__ __align__(16) u64 xs[18*18];
    __shared__ int st[4][8][32];

    int tid  = threadIdx.x;
    int pair = tid & 31;
    int grp  = tid >> 5;
    int n  = blockIdx.z;
    int h0 = blockIdx.y * 16, w0 = blockIdx.x * 16;

    // fused halo pack: read 64 channel floats per halo pixel, pack sign bits
    const float* xn = x + (size_t)n*Cc*HW;
    for (int j = tid; j < 18*18; j += 256) {
        int lh = j / 18, lw = j - lh*18;
        int gh = h0 + lh - 1, gw = w0 + lw - 1;
        u64 v = 0ull;
        if (gh >= 0 && gh < Hh && gw >= 0 && gw < Wd) {
            const float* px = xn + gh*Wd + gw;
            unsigned la = 0, lb = 0, lc = 0, ld = 0;
            unsigned ha = 0, hb = 0, hc = 0, hd = 0;
            #pragma unroll
            for (int c = 0; c < 8; c++) {
                la |= (__float_as_uint(__ldg(px + (size_t)(c     )*HW)) >> 31) << (c);
                lb |= (__float_as_uint(__ldg(px + (size_t)(c +  8)*HW)) >> 31) << (c+8);
                lc |= (__float_as_uint(__ldg(px + (size_t)(c + 16)*HW)) >> 31) << (c+16);
                ld |= (__float_as_uint(__ldg(px + (size_t)(c + 24)*HW)) >> 31) << (c+24);
            }
            #pragma unroll
            for (int c = 0; c < 8; c++) {
                ha |= (__float_as_uint(__ldg(px + (size_t)(c + 32)*HW)) >> 31) << (c);
                hb |= (__float_as_uint(__ldg(px + (size_t)(c + 40)*HW)) >> 31) << (c+8);
                hc |= (__float_as_uint(__ldg(px + (size_t)(c + 48)*HW)) >> 31) << (c+16);
                hd |= (__float_as_uint(__ldg(px + (size_t)(c + 56)*HW)) >> 31) << (c+24);
            }
            unsigned lo = (la | lb) | (lc | ld);
            unsigned hi = (ha | hb) | (hc | hd);
            v = ((u64)hi << 32) | lo;
        }
        xs[j] = v;
    }

    int c0 = pair*2;
    u64 wb0[9], wb1[9];
    #pragma unroll
    for (int t = 0; t < 9; t++) {
        wb0[t] = g_wbits[c0*9 + t];
        wb1[t] = g_wbits[(c0+1)*9 + t];
    }
    __syncthreads();

    const bool wleft  = (w0 == 0);
    const bool wright = (w0 == Wd-16);
    int as0 = 0, ass0 = 0, as1 = 0, ass1 = 0;

    #pragma unroll
    for (int r = 0; r < 2; r++) {
        int ohl = grp*2 + r;
        int oh  = h0 + ohl;
        int rp  = (oh == 0) ? 1 : ((oh == Hh-1) ? 2 : 0);

        // lazy border constants (uniform per warp; interior rows skip)
        int base0 = 576, base1 = 576;
        if (rp == 1) {
            base0 -= WD0(0) + WD0(1) + WD0(2);
            base1 -= WD1(0) + WD1(1) + WD1(2);
        } else if (rp == 2) {
            base0 -= WD0(6) + WD0(7) + WD0(8);
            base1 -= WD1(6) + WD1(7) + WD1(8);
        }
        int cw0 = 0, cw1 = 0, ce0 = 0, ce1 = 0;
        if (wleft) {
            cw0 = WD0(3); cw1 = WD1(3);
            if (rp != 1) { cw0 += WD0(0); cw1 += WD1(0); }
            if (rp != 2) { cw0 += WD0(6); cw1 += WD1(6); }
        }
        if (wright) {
            ce0 = WD0(5); ce1 = WD1(5);
            if (rp != 1) { ce0 += WD0(2); ce1 += WD1(2); }
            if (rp != 2) { ce0 += WD0(8); ce1 += WD1(8); }
        }

        const u64* r0p = &xs[ohl*18];
        const u64* r1p = r0p + 18;
        const u64* r2p = r1p + 18;
        ulonglong2 p0 = *(const ulonglong2*)&r0p[0];
        ulonglong2 p1 = *(const ulonglong2*)&r1p[0];
        ulonglong2 p2 = *(const ulonglong2*)&r2p[0];
        u64 x00 = p0.x, x01 = p0.y;
        u64 x10 = p1.x, x11 = p1.y;
        u64 x20 = p2.x, x21 = p2.y;

        unsigned* op = ((unsigned*)g_conv) + ((size_t)n*HW + (size_t)oh*Wd + w0)*32 + pair;

        #pragma unroll
        for (int w = 0; w < 16; w += 2) {
            ulonglong2 a0 = *(const ulonglong2*)&r0p[w+2];
            ulonglong2 a1 = *(const ulonglong2*)&r1p[w+2];
            ulonglong2 a2 = *(const ulonglong2*)&r2p[w+2];

            int sA0 = base0 - 2*PC9(wb0, x00,x01,a0.x, x10,x11,a1.x, x20,x21,a2.x);
            int sA1 = base1 - 2*PC9(wb1, x00,x01,a0.x, x10,x11,a1.x, x20,x21,a2.x);
            int sB0 = base0 - 2*PC9(wb0, x01,a0.x,a0.y, x11,a1.x,a1.y, x21,a2.x,a2.y);
            int sB1 = base1 - 2*PC9(wb1, x01,a0.x,a0.y, x11,a1.x,a1.y, x21,a2.x,a2.y);

            if (w == 0 && wleft)    { sA0 -= cw0; sA1 -= cw1; }
            if (w == 14 && wright)  { sB0 -= ce0; sB1 -= ce1; }

            as0 += sA0 + sB0; ass0 += sA0*sA0 + sB0*sB0;
            as1 += sA1 + sB1; ass1 += sA1*sA1 + sB1*sB1;

            op[0]  = ((unsigned)sA0 & 0xFFFFu) | ((unsigned)sA1 << 16);
            op[32] = ((unsigned)sB0 & 0xFFFFu) | ((unsigned)sB1 << 16);
            op += 64;

            x00 = a0.x; x01 = a0.y;
            x10 = a1.x; x11 = a1.y;
            x20 = a2.x; x21 = a2.y;
        }
    }

    st[0][grp][pair] = as0; st[1][grp][pair] = ass0;
    st[2][grp][pair] = as1; st[3][grp][pair] = ass1;
    __syncthreads();
    if (grp == 0) {
        int bs0=0, bss0=0, bs1=0, bss1=0;
        #pragma unroll
        for (int g = 0; g < 8; g++) {
            bs0 += st[0][g][pair]; bss0 += st[1][g][pair];
            bs1 += st[2][g][pair]; bss1 += st[3][g][pair];
        }
        atomicAdd((unsigned long long*)&g_sum[c0],   (unsigned long long)(long long)bs0);
        atomicAdd((unsigned long long*)&g_ss[c0],    (unsigned long long)(long long)bss0);
        atomicAdd((unsigned long long*)&g_sum[c0+1], (unsigned long long)(long long)bs1);
        atomicAdd((unsigned long long*)&g_ss[c0+1],  (unsigned long long)(long long)bss1);
    }
}

// ---------------- K2: affine fold (incl. alpha) + hardtanh + residual ----------
__global__ __launch_bounds__(256) void apply_k(const float* __restrict__ x,
                                               const float* __restrict__ gamma,
                                               const float* __restrict__ beta,
                                               float* __restrict__ out) {
    __shared__ float sA[Cc], sB[Cc];
    int tid = threadIdx.x;
    if (tid < Cc) {
        int c = tid;
        float t = 0.f;
        #pragma unroll
        for (int j = 0; j < 18; j++) t += g_wasum[c*18 + j];
        double a    = (double)(t / 576.f);
        double mean = (double)g_sum[c] / (double)NHW;
        double ex2  = (double)g_ss[c]  / (double)NHW;
        double var  = a*a*(ex2 - mean*mean);
        double rs   = 1.0 / sqrt(var + BN_EPS);
        double g    = (double)gamma[c];
        sA[c] = (float)(a * rs * g);
        sB[c] = (float)((double)beta[c] - a * mean * rs * g);
    }
    __syncthreads();

    size_t P = (size_t)blockIdx.x*256 + tid;      // global pixel id
    int n = (int)(P / HW);
    int p = (int)(P - (size_t)n*HW);
    const uint4* cb = (const uint4*)g_conv + P*8;           // 128B of NHWC shorts
    const float* xb = x   + (size_t)n*Cc*HW + p;
    float*       ob = out + (size_t)n*Cc*HW + p;

    #pragma unroll
    for (int q = 0; q < 8; q++) {
        uint4 v = cb[q];
        #pragma unroll
        for (int w = 0; w < 4; w++) {
            uint32_t u = (&v.x)[w];
            int cA = (q*4 + w)*2;
            int sv0 = (int)((int32_t)(u << 16) >> 16);
            int sv1 = (int)((int32_t)u >> 16);
            float r0 = fminf(fmaxf(fmaf((float)sv0, sA[cA],   sB[cA]),   -1.f), 1.f);
            float r1 = fminf(fmaxf(fmaf((float)sv1, sA[cA+1], sB[cA+1]), -1.f), 1.f);
            ob[(size_t)cA*HW]     = r0 + xb[(size_t)cA*HW];
            ob[(size_t)(cA+1)*HW] = r1 + xb[(size_t)(cA+1)*HW];
        }
    }
}

// ---------------- launcher ------------------------------------------------------
extern "C" void kernel_launch(void* const* d_in, const int* in_sizes, int n_in,
                              void* d_out, int out_size) {
    const float* x     = (const float*)d_in[0];
    const float* W     = (const float*)d_in[1];
    const float* gamma = (const float*)d_in[2];
    const float* beta  = (const float*)d_in[3];
    float* out = (float*)d_out;

    packW_k<<<144, 256>>>(W);
    conv_k<<<dim3(7, 7, Nn), 256>>>(x);
    apply_k<<<NHW/256, 256>>>(x, gamma, beta, out);
}